// round 1
// baseline (speedup 1.0000x reference)
#include <cuda_runtime.h>
#include <math.h>

// Problem constants
#define NB 8
#define NN 2048
#define NC 128
#define NCH 64      // chunks per batch
#define CSZ 32      // chunk size (NCH*CSZ == NN)

// ---------------- scratch (device globals; no allocation) ----------------
__device__ float g_h[NB*NN*NC];        // h = text @ W
__device__ float g_s1[NB*NN];
__device__ float g_s2[NB*NN];
__device__ float g_s2s[NB*NN];         // sorted s2 (ascending)
__device__ int   g_perm[NB*NN];        // permutation of sort
__device__ float g_wA[NB*NN];          // e^{s2s - m2}
__device__ float g_wB[NB*NN];          // e^{0.2(s2s - m2)}
__device__ float g_m2[NB];
__device__ float g_chA[NB*(NCH+1)*NC]; // chunk sums -> exclusive prefixes; [64]=total
__device__ float g_chB[NB*(NCH+1)*NC];
__device__ float g_pa[NB*(NCH+1)];     // scalar exclusive prefixes; [64]=total
__device__ float g_pb[NB*(NCH+1)];

// ---------------- Kernel 1: GEMM h = text@W, fused s1/s2 ----------------
// Block tile 64x128 (full N), BK=16, 256 threads, 8x4 microtile.
__global__ void __launch_bounds__(256) gemm_kernel(const float* __restrict__ A,
                                                   const float* __restrict__ W,
                                                   const float* __restrict__ avec)
{
    __shared__ float As[16][64];
    __shared__ float Bs[16][128];
    const int b  = blockIdx.y;
    const int m0 = blockIdx.x * 64;
    const int tid = threadIdx.x;
    const int tx = tid & 31;          // N dir: 32 * 4 = 128
    const int ty = tid >> 5;          // M dir: 8 * 8 = 64
    const float* Ab = A + (size_t)(b*NN + m0) * NC;

    float acc[8][4];
#pragma unroll
    for (int i = 0; i < 8; i++)
#pragma unroll
        for (int j = 0; j < 4; j++) acc[i][j] = 0.f;

    const int ar = tid >> 2;          // 0..63
    const int ac = (tid & 3) * 4;     // 0,4,8,12

    for (int k0 = 0; k0 < 128; k0 += 16) {
        // load A tile (64x16), store transposed
        float4 av = *(const float4*)(Ab + (size_t)ar*NC + k0 + ac);
        As[ac+0][ar] = av.x; As[ac+1][ar] = av.y;
        As[ac+2][ar] = av.z; As[ac+3][ar] = av.w;
        // load W tile (16x128)
#pragma unroll
        for (int it = 0; it < 2; it++) {
            int idx = tid + 256*it;
            int brr = idx >> 5, bcc = (idx & 31) * 4;
            *(float4*)&Bs[brr][bcc] = *(const float4*)(W + (size_t)(k0+brr)*NC + bcc);
        }
        __syncthreads();
#pragma unroll
        for (int kk = 0; kk < 16; kk++) {
            float arv[8], brv[4];
#pragma unroll
            for (int i = 0; i < 8; i++) arv[i] = As[kk][ty*8+i];
#pragma unroll
            for (int j = 0; j < 4; j++) brv[j] = Bs[kk][tx*4+j];
#pragma unroll
            for (int i = 0; i < 8; i++)
#pragma unroll
                for (int j = 0; j < 4; j++) acc[i][j] = fmaf(arv[i], brv[j], acc[i][j]);
        }
        __syncthreads();
    }

    float a1[4], a2[4];
#pragma unroll
    for (int j = 0; j < 4; j++) { a1[j] = avec[tx*4+j]; a2[j] = avec[128 + tx*4+j]; }

#pragma unroll
    for (int i = 0; i < 8; i++) {
        int row = m0 + ty*8 + i;
        float4 v = make_float4(acc[i][0], acc[i][1], acc[i][2], acc[i][3]);
        *(float4*)(g_h + (size_t)(b*NN + row)*NC + tx*4) = v;
        float d1 = acc[i][0]*a1[0] + acc[i][1]*a1[1] + acc[i][2]*a1[2] + acc[i][3]*a1[3];
        float d2 = acc[i][0]*a2[0] + acc[i][1]*a2[1] + acc[i][2]*a2[2] + acc[i][3]*a2[3];
#pragma unroll
        for (int off = 16; off > 0; off >>= 1) {
            d1 += __shfl_down_sync(0xffffffffu, d1, off);
            d2 += __shfl_down_sync(0xffffffffu, d2, off);
        }
        if (tx == 0) { g_s1[b*NN + row] = d1; g_s2[b*NN + row] = d2; }
    }
}

// ---------------- Kernel 2: per-batch bitonic sort of s2 + weights ----------------
__global__ void __launch_bounds__(1024) sort_kernel()
{
    __shared__ float key[NN];
    __shared__ int   idx[NN];
    __shared__ float csA[NCH], csB[NCH];
    const int b = blockIdx.x, tid = threadIdx.x;

    for (int i = tid; i < NN; i += 1024) { key[i] = g_s2[b*NN + i]; idx[i] = i; }
    __syncthreads();

    for (int k2 = 2; k2 <= NN; k2 <<= 1) {
        for (int j = k2 >> 1; j > 0; j >>= 1) {
            for (int i = tid; i < NN; i += 1024) {
                int ixj = i ^ j;
                if (ixj > i) {
                    bool up = ((i & k2) == 0);
                    float ka = key[i], kb = key[ixj];
                    bool sw = up ? (ka > kb) : (ka < kb);
                    if (sw) {
                        key[i] = kb; key[ixj] = ka;
                        int t = idx[i]; idx[i] = idx[ixj]; idx[ixj] = t;
                    }
                }
            }
            __syncthreads();
        }
    }

    float m2v = key[NN-1];
    if (tid == 0) g_m2[b] = m2v;

    float wa[2], wb[2];
#pragma unroll
    for (int u = 0; u < 2; u++) {
        int i = tid + 1024*u;
        float s = key[i] - m2v;
        wa[u] = expf(s);
        wb[u] = expf(0.2f * s);
        g_s2s[b*NN + i]  = key[i];
        g_perm[b*NN + i] = idx[i];
        g_wA[b*NN + i]   = wa[u];
        g_wB[b*NN + i]   = wb[u];
    }
    __syncthreads();
    float* fidx = (float*)idx;   // reuse idx storage for wB
#pragma unroll
    for (int u = 0; u < 2; u++) {
        int i = tid + 1024*u;
        key[i]  = wa[u];
        fidx[i] = wb[u];
    }
    __syncthreads();
    if (tid < NCH) {
        float ca = 0.f, cb = 0.f;
#pragma unroll 8
        for (int r = 0; r < CSZ; r++) { ca += key[tid*CSZ + r]; cb += fidx[tid*CSZ + r]; }
        csA[tid] = ca; csB[tid] = cb;
    }
    __syncthreads();
    if (tid == 0) {
        float ra = 0.f, rb = 0.f;
        for (int c = 0; c < NCH; c++) {
            g_pa[b*(NCH+1)+c] = ra; g_pb[b*(NCH+1)+c] = rb;
            ra += csA[c]; rb += csB[c];
        }
        g_pa[b*(NCH+1)+NCH] = ra; g_pb[b*(NCH+1)+NCH] = rb;
    }
}

// ---------------- Kernel 3: vector chunk sums ----------------
__global__ void __launch_bounds__(128) chunk_kernel()
{
    const int b = blockIdx.y, c = blockIdx.x, f = threadIdx.x;
    const int base = b*NN + c*CSZ;
    float aA = 0.f, aB = 0.f;
#pragma unroll 4
    for (int r = 0; r < CSZ; r++) {
        int j = g_perm[base + r];
        float wa = g_wA[base + r], wb = g_wB[base + r];
        float hv = g_h[(size_t)(b*NN + j)*NC + f];
        aA = fmaf(wa, hv, aA);
        aB = fmaf(wb, hv, aB);
    }
    g_chA[(size_t)(b*(NCH+1)+c)*NC + f] = aA;
    g_chB[(size_t)(b*(NCH+1)+c)*NC + f] = aB;
}

// ---------------- Kernel 4: exclusive scan over chunks ----------------
__global__ void __launch_bounds__(128) scan_kernel()
{
    const int b = blockIdx.x, f = threadIdx.x;
    float run = 0.f;
    for (int c0 = 0; c0 < NCH; c0 += 8) {
        float v[8];
#pragma unroll
        for (int u = 0; u < 8; u++) v[u] = g_chA[(size_t)(b*(NCH+1)+c0+u)*NC + f];
#pragma unroll
        for (int u = 0; u < 8; u++) { g_chA[(size_t)(b*(NCH+1)+c0+u)*NC + f] = run; run += v[u]; }
    }
    g_chA[(size_t)(b*(NCH+1)+NCH)*NC + f] = run;
    run = 0.f;
    for (int c0 = 0; c0 < NCH; c0 += 8) {
        float v[8];
#pragma unroll
        for (int u = 0; u < 8; u++) v[u] = g_chB[(size_t)(b*(NCH+1)+c0+u)*NC + f];
#pragma unroll
        for (int u = 0; u < 8; u++) { g_chB[(size_t)(b*(NCH+1)+c0+u)*NC + f] = run; run += v[u]; }
    }
    g_chB[(size_t)(b*(NCH+1)+NCH)*NC + f] = run;
}

// ---------------- Kernel 5: per-query output ----------------
__global__ void __launch_bounds__(128) query_kernel(float* __restrict__ out)
{
    __shared__ float s2sh[NN];
    const int b = blockIdx.y, f = threadIdx.x;
    const int qbase = blockIdx.x * 16;
    for (int i = f; i < NN; i += 128) s2sh[i] = g_s2s[b*NN + i];
    __syncthreads();

    const float m2v = g_m2[b];
    const float taf = g_chA[(size_t)(b*(NCH+1)+NCH)*NC + f];
    const float tas = g_pa[b*(NCH+1)+NCH];

    for (int qi = 0; qi < 16; qi++) {
        const int i = qbase + qi;
        const float s1v = g_s1[b*NN + i];
        const float t = -s1v;
        // k = #{ j : s2s[j] <= t }   (uniform across block)
        int k = 0;
#pragma unroll
        for (int st = 2048; st > 0; st >>= 1) {
            int nk = k + st;
            if (nk <= NN && s2sh[nk-1] <= t) k = nk;
        }
        const int c = k >> 5, rem = k & 31;
        float accA = g_chA[(size_t)(b*(NCH+1)+c)*NC + f];
        float accB = g_chB[(size_t)(b*(NCH+1)+c)*NC + f];
        float sap = g_pa[b*(NCH+1)+c];
        float sbp = g_pb[b*(NCH+1)+c];
        const int base = b*NN + c*CSZ;
#pragma unroll 4
        for (int r = 0; r < rem; r++) {
            int j = g_perm[base + r];
            float wa = g_wA[base + r], wb = g_wB[base + r];
            float hv = g_h[(size_t)(b*NN + j)*NC + f];
            accA = fmaf(wa, hv, accA);
            accB = fmaf(wb, hv, accB);
            sap += wa; sbp += wb;
        }
        const float SA = taf - accA, SB = accB;
        const float sa = tas - sap,  sb = sbp;
        const float u = s1v + m2v;
        float hp;
        if (u > 0.f) {
            float inv = expf(-0.8f * u);
            hp = (SA + inv*SB) / (sa + inv*sb);
        } else {
            float fc = expf(0.8f * u);
            hp = (fc*SA + SB) / (fc*sa + sb);
        }
        const float hvi = g_h[(size_t)(b*NN + i)*NC + f];
        const float x = hp + 0.2f * hvi;
        out[(size_t)(b*NN + i)*NC + f] = (x > 0.f) ? x : expm1f(x);
    }
}

// ---------------- launch ----------------
extern "C" void kernel_launch(void* const* d_in, const int* in_sizes, int n_in,
                              void* d_out, int out_size)
{
    // robust input mapping by element count
    int iText = 0, iW = 2, iA = 3;
    for (int i = 0; i < n_in; i++) {
        if (in_sizes[i] == NB*NN*NC) iText = i;
        else if (in_sizes[i] == NC*NC) iW = i;
        else if (in_sizes[i] == 2*NC) iA = i;
    }
    const float* text = (const float*)d_in[iText];
    const float* W    = (const float*)d_in[iW];
    const float* avec = (const float*)d_in[iA];
    float* out = (float*)d_out;

    gemm_kernel<<<dim3(NN/64, NB), 256>>>(text, W, avec);
    sort_kernel<<<NB, 1024>>>();
    chunk_kernel<<<dim3(NCH, NB), 128>>>();
    scan_kernel<<<NB, 128>>>();
    query_kernel<<<dim3(NN/16, NB), 128>>>(out);
}

// round 2
// speedup vs baseline: 1.5767x; 1.5767x over previous
#include <cuda_runtime.h>
#include <math.h>

// Problem constants
#define NB 8
#define NN 2048
#define NC 128
#define NCH 64      // chunks per batch
#define CSZ 32      // chunk size (NCH*CSZ == NN)
#define NP (NN+1)   // prefix length 2049

// ---------------- scratch (device globals; no allocation) ----------------
__device__ float g_h[NB*NN*NC];        // h = text @ W
__device__ float g_s1[NB*NN];
__device__ float g_s2[NB*NN];
__device__ float g_s2s[NB*NN];         // sorted s2 (ascending)
__device__ int   g_perm[NB*NN];        // permutation of sort
__device__ float g_wA[NB*NN];          // e^{s2s - m2}
__device__ float g_wB[NB*NN];          // e^{0.2(s2s - m2)}
__device__ float g_m2[NB];
__device__ float g_chA[NB*(NCH+1)*NC]; // chunk sums -> exclusive prefixes; [64]=total
__device__ float g_chB[NB*(NCH+1)*NC];
__device__ float g_paf[NB*NP];         // full scalar exclusive prefix of wA; [2048]=total
__device__ float g_pbf[NB*NP];
__device__ float g_PA[NB*NP*NC];       // full vector prefix of wA*h
__device__ float g_PB[NB*NP*NC];

// ---------------- Kernel 1: GEMM h = text@W, fused s1/s2 ----------------
__global__ void __launch_bounds__(256) gemm_kernel(const float* __restrict__ A,
                                                   const float* __restrict__ W,
                                                   const float* __restrict__ avec)
{
    __shared__ float As[16][64];
    __shared__ float Bs[16][128];
    const int b  = blockIdx.y;
    const int m0 = blockIdx.x * 64;
    const int tid = threadIdx.x;
    const int tx = tid & 31;          // N dir: 32 * 4 = 128
    const int ty = tid >> 5;          // M dir: 8 * 8 = 64
    const float* Ab = A + (size_t)(b*NN + m0) * NC;

    float acc[8][4];
#pragma unroll
    for (int i = 0; i < 8; i++)
#pragma unroll
        for (int j = 0; j < 4; j++) acc[i][j] = 0.f;

    const int ar = tid >> 2;          // 0..63
    const int ac = (tid & 3) * 4;     // 0,4,8,12

    for (int k0 = 0; k0 < 128; k0 += 16) {
        float4 av = *(const float4*)(Ab + (size_t)ar*NC + k0 + ac);
        As[ac+0][ar] = av.x; As[ac+1][ar] = av.y;
        As[ac+2][ar] = av.z; As[ac+3][ar] = av.w;
#pragma unroll
        for (int it = 0; it < 2; it++) {
            int idx = tid + 256*it;
            int brr = idx >> 5, bcc = (idx & 31) * 4;
            *(float4*)&Bs[brr][bcc] = *(const float4*)(W + (size_t)(k0+brr)*NC + bcc);
        }
        __syncthreads();
#pragma unroll
        for (int kk = 0; kk < 16; kk++) {
            float arv[8], brv[4];
#pragma unroll
            for (int i = 0; i < 8; i++) arv[i] = As[kk][ty*8+i];
#pragma unroll
            for (int j = 0; j < 4; j++) brv[j] = Bs[kk][tx*4+j];
#pragma unroll
            for (int i = 0; i < 8; i++)
#pragma unroll
                for (int j = 0; j < 4; j++) acc[i][j] = fmaf(arv[i], brv[j], acc[i][j]);
        }
        __syncthreads();
    }

    float a1[4], a2[4];
#pragma unroll
    for (int j = 0; j < 4; j++) { a1[j] = avec[tx*4+j]; a2[j] = avec[128 + tx*4+j]; }

#pragma unroll
    for (int i = 0; i < 8; i++) {
        int row = m0 + ty*8 + i;
        float4 v = make_float4(acc[i][0], acc[i][1], acc[i][2], acc[i][3]);
        *(float4*)(g_h + (size_t)(b*NN + row)*NC + tx*4) = v;
        float d1 = acc[i][0]*a1[0] + acc[i][1]*a1[1] + acc[i][2]*a1[2] + acc[i][3]*a1[3];
        float d2 = acc[i][0]*a2[0] + acc[i][1]*a2[1] + acc[i][2]*a2[2] + acc[i][3]*a2[3];
#pragma unroll
        for (int off = 16; off > 0; off >>= 1) {
            d1 += __shfl_down_sync(0xffffffffu, d1, off);
            d2 += __shfl_down_sync(0xffffffffu, d2, off);
        }
        if (tx == 0) { g_s1[b*NN + row] = d1; g_s2[b*NN + row] = d2; }
    }
}

// ---------------- Kernel 2: per-batch bitonic sort + weights + scalar prefixes ----------------
__global__ void __launch_bounds__(1024) sort_kernel()
{
    __shared__ float key[NN];
    __shared__ int   idx[NN];
    __shared__ float csA[NCH], csB[NCH];
    __shared__ float cpA[NCH+1], cpB[NCH+1];
    const int b = blockIdx.x, tid = threadIdx.x;

    for (int i = tid; i < NN; i += 1024) { key[i] = g_s2[b*NN + i]; idx[i] = i; }
    __syncthreads();

    for (int k2 = 2; k2 <= NN; k2 <<= 1) {
        for (int j = k2 >> 1; j > 0; j >>= 1) {
            for (int i = tid; i < NN; i += 1024) {
                int ixj = i ^ j;
                if (ixj > i) {
                    bool up = ((i & k2) == 0);
                    float ka = key[i], kb = key[ixj];
                    bool sw = up ? (ka > kb) : (ka < kb);
                    if (sw) {
                        key[i] = kb; key[ixj] = ka;
                        int t = idx[i]; idx[i] = idx[ixj]; idx[ixj] = t;
                    }
                }
            }
            __syncthreads();
        }
    }

    float m2v = key[NN-1];
    if (tid == 0) g_m2[b] = m2v;

    float wa[2], wb[2];
#pragma unroll
    for (int u = 0; u < 2; u++) {
        int i = tid + 1024*u;
        float s = key[i] - m2v;
        wa[u] = expf(s);
        wb[u] = expf(0.2f * s);
        g_s2s[b*NN + i]  = key[i];
        g_perm[b*NN + i] = idx[i];
        g_wA[b*NN + i]   = wa[u];
        g_wB[b*NN + i]   = wb[u];
    }
    __syncthreads();
    float* fidx = (float*)idx;   // reuse idx storage for wB
#pragma unroll
    for (int u = 0; u < 2; u++) {
        int i = tid + 1024*u;
        key[i]  = wa[u];
        fidx[i] = wb[u];
    }
    __syncthreads();
    if (tid < NCH) {
        float ca = 0.f, cb = 0.f;
#pragma unroll 8
        for (int r = 0; r < CSZ; r++) { ca += key[tid*CSZ + r]; cb += fidx[tid*CSZ + r]; }
        csA[tid] = ca; csB[tid] = cb;
    }
    __syncthreads();
    if (tid == 0) {
        float ra = 0.f, rb = 0.f;
        for (int c = 0; c < NCH; c++) {
            cpA[c] = ra; cpB[c] = rb;
            ra += csA[c]; rb += csB[c];
        }
        cpA[NCH] = ra; cpB[NCH] = rb;
        g_paf[b*NP + NN] = ra; g_pbf[b*NP + NN] = rb;
    }
    __syncthreads();
    // full scalar exclusive prefixes: one thread per chunk writes 32 entries
    if (tid < NCH) {
        float ra = cpA[tid], rb = cpB[tid];
#pragma unroll 8
        for (int r = 0; r < CSZ; r++) {
            int i = tid*CSZ + r;
            g_paf[b*NP + i] = ra; g_pbf[b*NP + i] = rb;
            ra += key[i]; rb += fidx[i];
        }
    }
}

// ---------------- Kernel 3: vector chunk sums ----------------
__global__ void __launch_bounds__(128) chunk_kernel()
{
    const int b = blockIdx.y, c = blockIdx.x, f = threadIdx.x;
    const int base = b*NN + c*CSZ;
    float aA = 0.f, aB = 0.f;
#pragma unroll 4
    for (int r = 0; r < CSZ; r++) {
        int j = g_perm[base + r];
        float wa = g_wA[base + r], wb = g_wB[base + r];
        float hv = g_h[(size_t)(b*NN + j)*NC + f];
        aA = fmaf(wa, hv, aA);
        aB = fmaf(wb, hv, aB);
    }
    g_chA[(size_t)(b*(NCH+1)+c)*NC + f] = aA;
    g_chB[(size_t)(b*(NCH+1)+c)*NC + f] = aB;
}

// ---------------- Kernel 4: warp-parallel exclusive scan over chunks ----------------
// grid (NB, 16), 256 threads = 8 warps; warp w handles feature f = by*8 + w
__global__ void __launch_bounds__(256) scan_kernel()
{
    const int b = blockIdx.x;
    const int w = threadIdx.x >> 5, lane = threadIdx.x & 31;
    const int f = blockIdx.y * 8 + w;
    const size_t base = (size_t)(b*(NCH+1))*NC + f;

    {
        float v0 = g_chA[base + (size_t)(lane*2)*NC];
        float v1 = g_chA[base + (size_t)(lane*2+1)*NC];
        float own = v0 + v1;
        float s = own;
#pragma unroll
        for (int off = 1; off < 32; off <<= 1) {
            float n = __shfl_up_sync(0xffffffffu, s, off);
            if (lane >= off) s += n;
        }
        float excl = s - own;
        g_chA[base + (size_t)(lane*2)*NC]   = excl;
        g_chA[base + (size_t)(lane*2+1)*NC] = excl + v0;
        if (lane == 31) g_chA[base + (size_t)NCH*NC] = s;
    }
    {
        float v0 = g_chB[base + (size_t)(lane*2)*NC];
        float v1 = g_chB[base + (size_t)(lane*2+1)*NC];
        float own = v0 + v1;
        float s = own;
#pragma unroll
        for (int off = 1; off < 32; off <<= 1) {
            float n = __shfl_up_sync(0xffffffffu, s, off);
            if (lane >= off) s += n;
        }
        float excl = s - own;
        g_chB[base + (size_t)(lane*2)*NC]   = excl;
        g_chB[base + (size_t)(lane*2+1)*NC] = excl + v0;
        if (lane == 31) g_chB[base + (size_t)NCH*NC] = s;
    }
}

// ---------------- Kernel 5: expand full vector prefixes ----------------
__global__ void __launch_bounds__(128) expand_kernel()
{
    __shared__ float wa[CSZ], wb[CSZ];
    __shared__ int js[CSZ];
    const int b = blockIdx.y, c = blockIdx.x, f = threadIdx.x;
    const int base = b*NN + c*CSZ;
    if (f < CSZ) {
        wa[f] = g_wA[base + f];
        wb[f] = g_wB[base + f];
        js[f] = g_perm[base + f];
    }
    __syncthreads();

    float runA = g_chA[(size_t)(b*(NCH+1)+c)*NC + f];
    float runB = g_chB[(size_t)(b*(NCH+1)+c)*NC + f];
    size_t p = (size_t)(b*NP + c*CSZ)*NC + f;
#pragma unroll
    for (int r = 0; r < CSZ; r++) {
        g_PA[p] = runA;
        g_PB[p] = runB;
        float hv = g_h[(size_t)(b*NN + js[r])*NC + f];
        runA = fmaf(wa[r], hv, runA);
        runB = fmaf(wb[r], hv, runB);
        p += NC;
    }
    if (c == NCH-1) { g_PA[p] = runA; g_PB[p] = runB; }
}

// ---------------- Kernel 6: per-query output (no residual gathers) ----------------
__global__ void __launch_bounds__(128) query_kernel(float* __restrict__ out)
{
    __shared__ float s2sh[NN];
    __shared__ int   ks[16];
    __shared__ float s1s[16];
    const int b = blockIdx.y, f = threadIdx.x;
    const int qbase = blockIdx.x * 16;
    for (int i = f; i < NN; i += 128) s2sh[i] = g_s2s[b*NN + i];
    __syncthreads();

    if (f < 16) {
        const int i = qbase + f;
        const float s1v = g_s1[b*NN + i];
        s1s[f] = s1v;
        const float t = -s1v;
        int k = 0;
#pragma unroll
        for (int st = 2048; st > 0; st >>= 1) {
            int nk = k + st;
            if (nk <= NN && s2sh[nk-1] <= t) k = nk;
        }
        ks[f] = k;
    }
    __syncthreads();

    const float m2v = g_m2[b];
    const float taf = g_chA[(size_t)(b*(NCH+1)+NCH)*NC + f];
    const float tas = g_paf[b*NP + NN];

#pragma unroll 4
    for (int qi = 0; qi < 16; qi++) {
        const int i = qbase + qi;
        const int k = ks[qi];
        const float s1v = s1s[qi];
        const float PAk = g_PA[(size_t)(b*NP + k)*NC + f];
        const float PBk = g_PB[(size_t)(b*NP + k)*NC + f];
        const float sap = g_paf[b*NP + k];
        const float sbp = g_pbf[b*NP + k];
        const float SA = taf - PAk, SB = PBk;
        const float sa = tas - sap, sb = sbp;
        const float u = s1v + m2v;
        float hp;
        if (u > 0.f) {
            float inv = expf(-0.8f * u);
            hp = (SA + inv*SB) / (sa + inv*sb);
        } else {
            float fc = expf(0.8f * u);
            hp = (fc*SA + SB) / (fc*sa + sb);
        }
        const float hvi = g_h[(size_t)(b*NN + i)*NC + f];
        const float x = hp + 0.2f * hvi;
        out[(size_t)(b*NN + i)*NC + f] = (x > 0.f) ? x : expm1f(x);
    }
}

// ---------------- launch ----------------
extern "C" void kernel_launch(void* const* d_in, const int* in_sizes, int n_in,
                              void* d_out, int out_size)
{
    int iText = 0, iW = 2, iA = 3;
    for (int i = 0; i < n_in; i++) {
        if (in_sizes[i] == NB*NN*NC) iText = i;
        else if (in_sizes[i] == NC*NC) iW = i;
        else if (in_sizes[i] == 2*NC) iA = i;
    }
    const float* text = (const float*)d_in[iText];
    const float* W    = (const float*)d_in[iW];
    const float* avec = (const float*)d_in[iA];
    float* out = (float*)d_out;

    gemm_kernel<<<dim3(NN/64, NB), 256>>>(text, W, avec);
    sort_kernel<<<NB, 1024>>>();
    chunk_kernel<<<dim3(NCH, NB), 128>>>();
    scan_kernel<<<dim3(NB, 16), 256>>>();
    expand_kernel<<<dim3(NCH, NB), 128>>>();
    query_kernel<<<dim3(NN/16, NB), 128>>>(out);
}

// round 3
// speedup vs baseline: 1.5899x; 1.0084x over previous
#include <cuda_runtime.h>
#include <math.h>

// Problem constants
#define NB 8
#define NN 2048
#define NC 128
#define NCH 64      // chunks per batch
#define CSZ 32      // chunk size (NCH*CSZ == NN)
#define NP (NN+1)   // prefix length 2049

// ---------------- scratch (device globals; no allocation) ----------------
__device__ float g_h[NB*NN*NC];        // h = text @ W
__device__ float g_s1[NB*NN];
__device__ float g_s2[NB*NN];
__device__ float g_s2s[NB*NN];         // sorted s2 (ascending)
__device__ int   g_perm[NB*NN];        // permutation of sort
__device__ float g_wA[NB*NN];          // e^{s2s - m2}
__device__ float g_wB[NB*NN];          // e^{0.2(s2s - m2)}
__device__ float g_m2[NB];
__device__ float g_chA[NB*(NCH+1)*NC]; // inclusive chunk sums; [NCH]=grand total (by expand)
__device__ float g_chB[NB*(NCH+1)*NC];
__device__ float g_paf[NB*NP];         // full scalar exclusive prefix of wA; [2048]=total
__device__ float g_pbf[NB*NP];
__device__ float g_PA[NB*NP*NC];       // full vector prefix of wA*h
__device__ float g_PB[NB*NP*NC];

// ---------------- f32x2 packed-FMA helpers (sm_103a FFMA2) ----------------
__device__ __forceinline__ unsigned long long pack2(float x, float y) {
    unsigned long long r;
    asm("mov.b64 %0, {%1, %2};" : "=l"(r) : "f"(x), "f"(y));
    return r;
}
__device__ __forceinline__ void unpack2(unsigned long long v, float& x, float& y) {
    asm("mov.b64 {%0, %1}, %2;" : "=f"(x), "=f"(y) : "l"(v));
}
__device__ __forceinline__ void ffma2(unsigned long long& d, unsigned long long a, unsigned long long b) {
    asm("fma.rn.f32x2 %0, %1, %2, %0;" : "+l"(d) : "l"(a), "l"(b));
}

// ---------------- Kernel 1: GEMM h = text@W (f32x2), fused s1/s2 ----------------
__global__ void __launch_bounds__(256) gemm_kernel(const float* __restrict__ A,
                                                   const float* __restrict__ W,
                                                   const float* __restrict__ avec)
{
    __shared__ float As[16][64];
    __shared__ float Bs[16][128];
    const int b  = blockIdx.y;
    const int m0 = blockIdx.x * 64;
    const int tid = threadIdx.x;
    const int tx = tid & 31;          // N dir: 32 * 4 = 128
    const int ty = tid >> 5;          // M dir: 8 * 8 = 64
    const float* Ab = A + (size_t)(b*NN + m0) * NC;

    // acc2[p][j] holds rows (ty*8 + 2p, ty*8 + 2p + 1), col tx*4+j
    unsigned long long acc2[4][4];
#pragma unroll
    for (int p = 0; p < 4; p++)
#pragma unroll
        for (int j = 0; j < 4; j++) acc2[p][j] = 0ull;

    const int ar = tid >> 2;          // 0..63
    const int ac = (tid & 3) * 4;     // 0,4,8,12

    for (int k0 = 0; k0 < 128; k0 += 16) {
        float4 av = *(const float4*)(Ab + (size_t)ar*NC + k0 + ac);
        As[ac+0][ar] = av.x; As[ac+1][ar] = av.y;
        As[ac+2][ar] = av.z; As[ac+3][ar] = av.w;
#pragma unroll
        for (int it = 0; it < 2; it++) {
            int idx = tid + 256*it;
            int brr = idx >> 5, bcc = (idx & 31) * 4;
            *(float4*)&Bs[brr][bcc] = *(const float4*)(W + (size_t)(k0+brr)*NC + bcc);
        }
        __syncthreads();
#pragma unroll
        for (int kk = 0; kk < 16; kk++) {
            float4 a03 = *(const float4*)&As[kk][ty*8];
            float4 a47 = *(const float4*)&As[kk][ty*8 + 4];
            float4 bv  = *(const float4*)&Bs[kk][tx*4];
            unsigned long long ap[4];
            ap[0] = pack2(a03.x, a03.y); ap[1] = pack2(a03.z, a03.w);
            ap[2] = pack2(a47.x, a47.y); ap[3] = pack2(a47.z, a47.w);
            unsigned long long bd[4];
            bd[0] = pack2(bv.x, bv.x); bd[1] = pack2(bv.y, bv.y);
            bd[2] = pack2(bv.z, bv.z); bd[3] = pack2(bv.w, bv.w);
#pragma unroll
            for (int p = 0; p < 4; p++)
#pragma unroll
                for (int j = 0; j < 4; j++) ffma2(acc2[p][j], ap[p], bd[j]);
        }
        __syncthreads();
    }

    // unpack
    float acc[8][4];
#pragma unroll
    for (int p = 0; p < 4; p++)
#pragma unroll
        for (int j = 0; j < 4; j++) unpack2(acc2[p][j], acc[2*p][j], acc[2*p+1][j]);

    float a1[4], a2[4];
#pragma unroll
    for (int j = 0; j < 4; j++) { a1[j] = avec[tx*4+j]; a2[j] = avec[128 + tx*4+j]; }

#pragma unroll
    for (int i = 0; i < 8; i++) {
        int row = m0 + ty*8 + i;
        float4 v = make_float4(acc[i][0], acc[i][1], acc[i][2], acc[i][3]);
        *(float4*)(g_h + (size_t)(b*NN + row)*NC + tx*4) = v;
        float d1 = acc[i][0]*a1[0] + acc[i][1]*a1[1] + acc[i][2]*a1[2] + acc[i][3]*a1[3];
        float d2 = acc[i][0]*a2[0] + acc[i][1]*a2[1] + acc[i][2]*a2[2] + acc[i][3]*a2[3];
#pragma unroll
        for (int off = 16; off > 0; off >>= 1) {
            d1 += __shfl_down_sync(0xffffffffu, d1, off);
            d2 += __shfl_down_sync(0xffffffffu, d2, off);
        }
        if (tx == 0) { g_s1[b*NN + row] = d1; g_s2[b*NN + row] = d2; }
    }
}

// ---------------- Kernel 2: per-batch bitonic sort + weights + scalar prefixes ----------------
__global__ void __launch_bounds__(1024) sort_kernel()
{
    __shared__ float key[NN];
    __shared__ int   idx[NN];
    __shared__ float csA[NCH], csB[NCH];
    __shared__ float cpA[NCH+1], cpB[NCH+1];
    const int b = blockIdx.x, tid = threadIdx.x;

    for (int i = tid; i < NN; i += 1024) { key[i] = g_s2[b*NN + i]; idx[i] = i; }
    __syncthreads();

    for (int k2 = 2; k2 <= NN; k2 <<= 1) {
        for (int j = k2 >> 1; j > 0; j >>= 1) {
            for (int i = tid; i < NN; i += 1024) {
                int ixj = i ^ j;
                if (ixj > i) {
                    bool up = ((i & k2) == 0);
                    float ka = key[i], kb = key[ixj];
                    bool sw = up ? (ka > kb) : (ka < kb);
                    if (sw) {
                        key[i] = kb; key[ixj] = ka;
                        int t = idx[i]; idx[i] = idx[ixj]; idx[ixj] = t;
                    }
                }
            }
            __syncthreads();
        }
    }

    float m2v = key[NN-1];
    if (tid == 0) g_m2[b] = m2v;

    float wa[2], wb[2];
#pragma unroll
    for (int u = 0; u < 2; u++) {
        int i = tid + 1024*u;
        float s = key[i] - m2v;
        wa[u] = expf(s);
        wb[u] = expf(0.2f * s);
        g_s2s[b*NN + i]  = key[i];
        g_perm[b*NN + i] = idx[i];
        g_wA[b*NN + i]   = wa[u];
        g_wB[b*NN + i]   = wb[u];
    }
    __syncthreads();
    float* fidx = (float*)idx;   // reuse idx storage for wB
#pragma unroll
    for (int u = 0; u < 2; u++) {
        int i = tid + 1024*u;
        key[i]  = wa[u];
        fidx[i] = wb[u];
    }
    __syncthreads();
    if (tid < NCH) {
        float ca = 0.f, cb = 0.f;
#pragma unroll 8
        for (int r = 0; r < CSZ; r++) { ca += key[tid*CSZ + r]; cb += fidx[tid*CSZ + r]; }
        csA[tid] = ca; csB[tid] = cb;
    }
    __syncthreads();
    if (tid == 0) {
        float ra = 0.f, rb = 0.f;
        for (int c = 0; c < NCH; c++) {
            cpA[c] = ra; cpB[c] = rb;
            ra += csA[c]; rb += csB[c];
        }
        cpA[NCH] = ra; cpB[NCH] = rb;
        g_paf[b*NP + NN] = ra; g_pbf[b*NP + NN] = rb;
    }
    __syncthreads();
    if (tid < NCH) {
        float ra = cpA[tid], rb = cpB[tid];
#pragma unroll 8
        for (int r = 0; r < CSZ; r++) {
            int i = tid*CSZ + r;
            g_paf[b*NP + i] = ra; g_pbf[b*NP + i] = rb;
            ra += key[i]; rb += fidx[i];
        }
    }
}

// ---------------- Kernel 3: vector chunk sums (inclusive, per chunk) ----------------
__global__ void __launch_bounds__(128) chunk_kernel()
{
    __shared__ int   js[CSZ];
    __shared__ float swa[CSZ], swb[CSZ];
    const int b = blockIdx.y, c = blockIdx.x, f = threadIdx.x;
    const int base = b*NN + c*CSZ;
    if (f < CSZ) {
        js[f]  = g_perm[base + f];
        swa[f] = g_wA[base + f];
        swb[f] = g_wB[base + f];
    }
    __syncthreads();
    float aA = 0.f, aB = 0.f;
#pragma unroll
    for (int r = 0; r < CSZ; r++) {
        float hv = g_h[(size_t)(b*NN + js[r])*NC + f];
        aA = fmaf(swa[r], hv, aA);
        aB = fmaf(swb[r], hv, aB);
    }
    g_chA[(size_t)(b*(NCH+1)+c)*NC + f] = aA;
    g_chB[(size_t)(b*(NCH+1)+c)*NC + f] = aB;
}

// ---------------- Kernel 4: expand full vector prefixes (inline chunk scan) ----------------
__global__ void __launch_bounds__(128) expand_kernel()
{
    __shared__ float wa[CSZ], wb[CSZ];
    __shared__ int js[CSZ];
    const int b = blockIdx.y, c = blockIdx.x, f = threadIdx.x;
    const int base = b*NN + c*CSZ;
    if (f < CSZ) {
        wa[f] = g_wA[base + f];
        wb[f] = g_wB[base + f];
        js[f] = g_perm[base + f];
    }
    __syncthreads();

    // exclusive chunk base: sequential sum of predecessor chunk sums (bit-stable order)
    float runA = 0.f, runB = 0.f;
    const size_t chbase = (size_t)(b*(NCH+1))*NC + f;
    for (int cp = 0; cp < c; cp++) {
        runA += g_chA[chbase + (size_t)cp*NC];
        runB += g_chB[chbase + (size_t)cp*NC];
    }

    size_t p = (size_t)(b*NP + c*CSZ)*NC + f;
#pragma unroll
    for (int r = 0; r < CSZ; r++) {
        g_PA[p] = runA;
        g_PB[p] = runB;
        float hv = g_h[(size_t)(b*NN + js[r])*NC + f];
        runA = fmaf(wa[r], hv, runA);
        runB = fmaf(wb[r], hv, runB);
        p += NC;
    }
    if (c == NCH-1) {
        g_PA[p] = runA; g_PB[p] = runB;
        g_chA[chbase + (size_t)NCH*NC] = runA;   // grand total for query
    }
}

// ---------------- Kernel 5: per-query output (no residual gathers) ----------------
__global__ void __launch_bounds__(128) query_kernel(float* __restrict__ out)
{
    __shared__ float s2sh[NN];
    __shared__ int   ks[16];
    __shared__ float s1s[16];
    const int b = blockIdx.y, f = threadIdx.x;
    const int qbase = blockIdx.x * 16;
    for (int i = f; i < NN; i += 128) s2sh[i] = g_s2s[b*NN + i];
    __syncthreads();

    if (f < 16) {
        const int i = qbase + f;
        const float s1v = g_s1[b*NN + i];
        s1s[f] = s1v;
        const float t = -s1v;
        int k = 0;
#pragma unroll
        for (int st = 2048; st > 0; st >>= 1) {
            int nk = k + st;
            if (nk <= NN && s2sh[nk-1] <= t) k = nk;
        }
        ks[f] = k;
    }
    __syncthreads();

    const float m2v = g_m2[b];
    const float taf = g_chA[(size_t)(b*(NCH+1)+NCH)*NC + f];
    const float tas = g_paf[b*NP + NN];

#pragma unroll 4
    for (int qi = 0; qi < 16; qi++) {
        const int i = qbase + qi;
        const int k = ks[qi];
        const float s1v = s1s[qi];
        const float PAk = g_PA[(size_t)(b*NP + k)*NC + f];
        const float PBk = g_PB[(size_t)(b*NP + k)*NC + f];
        const float sap = g_paf[b*NP + k];
        const float sbp = g_pbf[b*NP + k];
        const float SA = taf - PAk, SB = PBk;
        const float sa = tas - sap, sb = sbp;
        const float u = s1v + m2v;
        float hp;
        if (u > 0.f) {
            float inv = expf(-0.8f * u);
            hp = (SA + inv*SB) / (sa + inv*sb);
        } else {
            float fc = expf(0.8f * u);
            hp = (fc*SA + SB) / (fc*sa + sb);
        }
        const float hvi = g_h[(size_t)(b*NN + i)*NC + f];
        const float x = hp + 0.2f * hvi;
        out[(size_t)(b*NN + i)*NC + f] = (x > 0.f) ? x : expm1f(x);
    }
}

// ---------------- launch ----------------
extern "C" void kernel_launch(void* const* d_in, const int* in_sizes, int n_in,
                              void* d_out, int out_size)
{
    int iText = 0, iW = 2, iA = 3;
    for (int i = 0; i < n_in; i++) {
        if (in_sizes[i] == NB*NN*NC) iText = i;
        else if (in_sizes[i] == NC*NC) iW = i;
        else if (in_sizes[i] == 2*NC) iA = i;
    }
    const float* text = (const float*)d_in[iText];
    const float* W    = (const float*)d_in[iW];
    const float* avec = (const float*)d_in[iA];
    float* out = (float*)d_out;

    gemm_kernel<<<dim3(NN/64, NB), 256>>>(text, W, avec);
    sort_kernel<<<NB, 1024>>>();
    chunk_kernel<<<dim3(NCH, NB), 128>>>();
    expand_kernel<<<dim3(NCH, NB), 128>>>();
    query_kernel<<<dim3(NN/16, NB), 128>>>(out);
}